// round 16
// baseline (speedup 1.0000x reference)
#include <cuda_runtime.h>

#define MAXD 365
#define NREP 8            // shared-hist replicas (even warps: (wid>>1)&7)
#define RSTR 369          // replica stride (mod 32 = 17: decorrelates banks)
#define NTHR 512
#define NBLK 444          // 3 blocks/SM * 148 SMs
#define NWRP (NTHR / 32)
#define CSH32 26          // shared pack: [31:26] count, [25:0] exp*8192
#define CSH64 50          // global pack: [63:50] count, [49:0] exp*8192
#define FIX_SCALE 8192.f
#define FIX_INV   (1.f / 8192.f)

__device__ float    g_S[MAXD];
__device__ unsigned g_M[MAXD];
__device__ float    g_sey;
__device__ unsigned g_done;
__device__ unsigned long long g_scr[NBLK * MAXD];   // per-block global hist scratch

__global__ void __launch_bounds__(NTHR, 3)
cox_split_kernel(const float* __restrict__ pred,
                 const int*   __restrict__ dur,
                 const int*   __restrict__ ev,
                 float* __restrict__ out,
                 int n)
{
    __shared__ unsigned sH[NREP * RSTR];
    __shared__ float    wA[NWRP];
    __shared__ unsigned sIsLast;

    const int t    = threadIdx.x;
    const int lane = t & 31, wid = t >> 5;
    const int rb   = ((wid >> 1) & (NREP - 1)) * RSTR;
    const bool useShared = (wid & 1) == 0;
    unsigned long long* myScr = &g_scr[blockIdx.x * MAXD];
    const int nv   = n >> 2;
    const int stride = NBLK * NTHR;

    for (int i = t; i < NREP * RSTR; i += NTHR) sH[i] = 0u;
    for (int i = t; i < MAXD; i += NTHR) myScr[i] = 0ull;   // replay-safe zero
    __syncthreads();

    float sey = 0.f;

    // ==== single pass: even warps -> shared ATOMS, odd warps -> global REDG ====
    {
        const float4* p4 = (const float4*)pred;
        const int4*   d4 = (const int4*)dur;
        const int4*   e4 = (const int4*)ev;
        for (int i = blockIdx.x * NTHR + t; i < nv; i += stride) {
            float4 y = p4[i];
            int4   d = d4[i];
            int4   e = e4[i];
            #pragma unroll
            for (int k = 0; k < 4; k++) {
                float yy = (&y.x)[k];
                unsigned dd = min((unsigned)(&d.x)[k], (unsigned)(MAXD - 1));
                unsigned ec = (unsigned)(&e.x)[k];
                float x  = fminf(fmaxf(yy, -20.f), 20.f);
                float ex = __expf(x);
                unsigned fx = (unsigned)__float2uint_rn(ex * FIX_SCALE);
                if (useShared) {
                    atomicAdd(&sH[rb + dd], (ec << CSH32) + fx);
                } else {
                    atomicAdd(&myScr[dd],
                              ((unsigned long long)ec << CSH64) + (unsigned long long)fx);
                }
                sey += (float)ec * yy;
            }
        }
        for (int s = (nv << 2) + blockIdx.x * NTHR + t; s < n; s += stride) {
            float yy = pred[s];
            unsigned dd = min((unsigned)dur[s], (unsigned)(MAXD - 1));
            unsigned ec = (unsigned)ev[s];
            float x  = fminf(fmaxf(yy, -20.f), 20.f);
            float ex = __expf(x);
            unsigned fx = (unsigned)__float2uint_rn(ex * FIX_SCALE);
            if (useShared) {
                atomicAdd(&sH[rb + dd], (ec << CSH32) + fx);
            } else {
                atomicAdd(&myScr[dd],
                          ((unsigned long long)ec << CSH64) + (unsigned long long)fx);
            }
            sey += (float)ec * yy;
        }
    }

    // block-reduce sey -> global
    #pragma unroll
    for (int o = 16; o; o >>= 1)
        sey += __shfl_down_sync(0xffffffffu, sey, o);
    if (lane == 0) wA[wid] = sey;
    __syncthreads();        // also orders odd warps' global REDG for the flush reads
    if (t == 0) {
        float a = 0.f;
        #pragma unroll
        for (int w = 0; w < NWRP; w++) a += wA[w];
        atomicAdd(&g_sey, a);
    }

    // flush: shared replicas + this block's global scratch -> one atomic per bucket
    const unsigned L32 = (1u << CSH32) - 1u;
    const unsigned long long L64 = (1ull << CSH64) - 1ull;
    for (int i = t; i < MAXD; i += NTHR) {
        unsigned long long lo = 0ull;
        unsigned m = 0u;
        #pragma unroll
        for (int r = 0; r < NREP; r++) {
            unsigned v = sH[r * RSTR + i];
            lo += (unsigned long long)(v & L32);
            m  += v >> CSH32;
        }
        unsigned long long gv = myScr[i];
        lo += gv & L64;
        m  += (unsigned)(gv >> CSH64);
        if (lo) atomicAdd(&g_S[i], (float)lo * FIX_INV);
        if (m)  atomicAdd(&g_M[i], m);
    }

    // ================= last-block finalize =================
    __threadfence();
    if (t == 0) {
        unsigned ticket = atomicAdd(&g_done, 1u);
        sIsLast = (ticket == (unsigned)(NBLK - 1)) ? 1u : 0u;
    }
    __syncthreads();
    if (!sIsLast) return;

    float*    scan = (float*)sH;                // [0..511]
    float*    redF = scan + 512;                // [0..511]
    unsigned* redN = (unsigned*)(scan + 1024);  // [0..511]

    float    s = (t < MAXD) ? __ldcg(&g_S[t]) : 0.f;
    unsigned m = (t < MAXD) ? __ldcg(&g_M[t]) : 0u;
    __syncthreads();
    scan[t] = s;
    __syncthreads();

    // Hillis-Steele inclusive suffix scan: scan[t] = sum_{j>=t} S[j]
    #pragma unroll
    for (int off = 1; off < NTHR; off <<= 1) {
        float v = (t + off < NTHR) ? scan[t + off] : 0.f;
        __syncthreads();
        scan[t] += v;
        __syncthreads();
    }

    float lg = logf(fmaxf(scan[t], 1e-12f));
    __syncthreads();
    scan[t] = (t < MAXD) ? lg : 0.f;        // logR LUT (dead corner)
    redF[t] = (float)m * ((t < MAXD) ? lg : 0.f);
    redN[t] = m;
    __syncthreads();

    #pragma unroll
    for (int off = NTHR / 2; off; off >>= 1) {
        if (t < off) {
            redF[t] += redF[t + off];
            redN[t] += redN[t + off];
        }
        __syncthreads();
    }

    unsigned nev = redN[0];

    if (nev > 0u) {
        if (t == 0) {
            float total_ll = __ldcg(&g_sey) - redF[0];
            out[0] = -total_ll / fmaxf((float)nev, 1.f);
        }
    } else {
        // dead-in-practice corner: e.sum()==0 -> e := 1e-8 everywhere
        float slr = 0.f, syl = 0.f;
        for (int i = t; i < n; i += NTHR) {
            unsigned dd = min((unsigned)dur[i], (unsigned)(MAXD - 1));
            slr += scan[dd];
            syl += pred[i];
        }
        #pragma unroll
        for (int o = 16; o; o >>= 1) {
            slr += __shfl_down_sync(0xffffffffu, slr, o);
            syl += __shfl_down_sync(0xffffffffu, syl, o);
        }
        if (lane == 0) { wA[wid] = slr; redF[wid] = syl; }
        __syncthreads();
        if (t == 0) {
            float tot = 0.f, sy = 0.f;
            #pragma unroll
            for (int w = 0; w < NWRP; w++) { tot += wA[w]; sy += redF[w]; }
            float total_ll = 1e-8f * (sy - tot);
            float n_events = fmaxf(1e-8f * (float)n, 1.f);
            out[0] = -total_ll / n_events;
        }
    }

    // re-zero globals for next graph replay (scratch re-zeroed per block at entry)
    __syncthreads();
    for (int i = t; i < MAXD; i += NTHR) { g_S[i] = 0.f; g_M[i] = 0u; }
    if (t == 0) { g_sey = 0.f; g_done = 0u; }
}

extern "C" void kernel_launch(void* const* d_in, const int* in_sizes, int n_in,
                              void* d_out, int out_size)
{
    const float* pred = (const float*)d_in[0];
    const int*   dur  = (const int*)d_in[1];
    const int*   ev   = (const int*)d_in[2];
    int n = in_sizes[0];

    cox_split_kernel<<<NBLK, NTHR>>>(pred, dur, ev, (float*)d_out, n);
}

// round 17
// speedup vs baseline: 1.6030x; 1.6030x over previous
#include <cuda_runtime.h>

#define MAXD 365
#define NREP 8            // histogram replicas (warp-pair selects)
#define RSTR 369          // replica stride (mod 32 = 17: decorrelates banks)
#define NTHR 512
#define NBLK 444          // 3 blocks/SM * 148 SMs
#define NWRP (NTHR / 32)
#define CNT_SHIFT 26      // [31:26] event count, [25:0] fixed-point exp sum
#define FIX_SCALE 8192.f
#define FIX_INV   (1.f / 8192.f)
#define STAGE 1024        // elements per TMA stage
#define STG_B (STAGE * 4) // bytes per array per stage
#define TX_BYTES (3 * STG_B)

__device__ float    g_S[MAXD];
__device__ unsigned g_M[MAXD];
__device__ float    g_sey;
__device__ unsigned g_done;

__global__ void __launch_bounds__(NTHR, 3)
cox_tma_kernel(const float* __restrict__ pred,
               const int*   __restrict__ dur,
               const int*   __restrict__ ev,
               float* __restrict__ out,
               int n)
{
    __shared__ unsigned sH[NREP * RSTR];
    __shared__ alignas(16) float sP[2][STAGE];
    __shared__ alignas(16) int   sD[2][STAGE];
    __shared__ alignas(16) int   sE[2][STAGE];
    __shared__ alignas(8) unsigned long long mbar[2];
    __shared__ float    wA[NWRP];
    __shared__ unsigned sIsLast;

    const int t    = threadIdx.x;
    const int lane = t & 31, wid = t >> 5;
    const int rb   = ((wid >> 1) & (NREP - 1)) * RSTR;
    const int bid  = blockIdx.x;

    for (int i = t; i < NREP * RSTR; i += NTHR) sH[i] = 0u;

    if (t == 0) {
        #pragma unroll
        for (int b = 0; b < 2; b++) {
            unsigned mb = (unsigned)__cvta_generic_to_shared(&mbar[b]);
            asm volatile("mbarrier.init.shared.b64 [%0], 1;" :: "r"(mb) : "memory");
        }
        asm volatile("fence.proxy.async.shared::cta;" ::: "memory");
    }
    __syncthreads();

    const int NSTG  = n / STAGE;            // full stages
    const int iters = (bid < NSTG) ? ((NSTG - 1 - bid) / NBLK + 1) : 0;

    // --- TMA issue (t==0 only): fill buffer `buf` with global stage `sg` ---
    #define ISSUE(buf, sg) do {                                                   \
        unsigned mb  = (unsigned)__cvta_generic_to_shared(&mbar[buf]);            \
        unsigned dP  = (unsigned)__cvta_generic_to_shared(&sP[buf][0]);           \
        unsigned dD  = (unsigned)__cvta_generic_to_shared(&sD[buf][0]);           \
        unsigned dE  = (unsigned)__cvta_generic_to_shared(&sE[buf][0]);           \
        size_t   off = (size_t)(sg) * STAGE;                                      \
        asm volatile("mbarrier.arrive.expect_tx.shared.b64 _, [%0], %1;"          \
                     :: "r"(mb), "r"((unsigned)TX_BYTES) : "memory");             \
        asm volatile("cp.async.bulk.shared::cta.global.mbarrier::complete_tx::bytes [%0], [%1], %2, [%3];" \
                     :: "r"(dP), "l"((const void*)(pred + off)), "r"((unsigned)STG_B), "r"(mb) : "memory"); \
        asm volatile("cp.async.bulk.shared::cta.global.mbarrier::complete_tx::bytes [%0], [%1], %2, [%3];" \
                     :: "r"(dD), "l"((const void*)(dur + off)), "r"((unsigned)STG_B), "r"(mb) : "memory");  \
        asm volatile("cp.async.bulk.shared::cta.global.mbarrier::complete_tx::bytes [%0], [%1], %2, [%3];" \
                     :: "r"(dE), "l"((const void*)(ev + off)), "r"((unsigned)STG_B), "r"(mb) : "memory");   \
    } while (0)

    #define WAITP(buf, p) do {                                                    \
        unsigned mb = (unsigned)__cvta_generic_to_shared(&mbar[buf]);             \
        unsigned done = 0;                                                        \
        while (!done) {                                                           \
            asm volatile("{\n\t.reg .pred P1;\n\t"                                \
                "mbarrier.try_wait.parity.acquire.cta.shared::cta.b64 P1, [%1], %2, 0x989680;\n\t" \
                "selp.b32 %0, 1, 0, P1;\n\t}"                                     \
                : "=r"(done) : "r"(mb), "r"((unsigned)(p)) : "memory");           \
        }                                                                         \
    } while (0)

    if (t == 0) {
        if (iters > 0) ISSUE(0, bid);
        if (iters > 1) ISSUE(1, bid + NBLK);
    }

    float sey = 0.f;
    int ph0 = 0, ph1 = 0;

    for (int i = 0; i < iters; i++) {
        const int buf = i & 1;
        if (buf == 0) { WAITP(0, ph0); ph0 ^= 1; }
        else          { WAITP(1, ph1); ph1 ^= 1; }

        const float2* pp = (const float2*)sP[buf];
        const int2*   dp = (const int2*)sD[buf];
        const int2*   ep = (const int2*)sE[buf];
        float2 y = pp[t];
        int2   d = dp[t];
        int2   e = ep[t];

        {
            unsigned dd = min((unsigned)d.x, (unsigned)(MAXD - 1));
            unsigned ec = (unsigned)e.x;
            float x  = fminf(fmaxf(y.x, -20.f), 20.f);
            unsigned pk = (ec << CNT_SHIFT) + (unsigned)__float2uint_rn(__expf(x) * FIX_SCALE);
            atomicAdd(&sH[rb + dd], pk);
            sey += (float)ec * y.x;
        }
        {
            unsigned dd = min((unsigned)d.y, (unsigned)(MAXD - 1));
            unsigned ec = (unsigned)e.y;
            float x  = fminf(fmaxf(y.y, -20.f), 20.f);
            unsigned pk = (ec << CNT_SHIFT) + (unsigned)__float2uint_rn(__expf(x) * FIX_SCALE);
            atomicAdd(&sH[rb + dd], pk);
            sey += (float)ec * y.y;
        }

        __syncthreads();                       // all reads of `buf` done
        if (t == 0 && i + 2 < iters) ISSUE(buf, bid + (i + 2) * NBLK);
    }

    // scalar tail (elements beyond NSTG*STAGE)
    for (int s = NSTG * STAGE + bid * NTHR + t; s < n; s += NBLK * NTHR) {
        float yy = pred[s];
        unsigned dd = min((unsigned)dur[s], (unsigned)(MAXD - 1));
        unsigned ec = (unsigned)ev[s];
        float x  = fminf(fmaxf(yy, -20.f), 20.f);
        unsigned pk = (ec << CNT_SHIFT) + (unsigned)__float2uint_rn(__expf(x) * FIX_SCALE);
        atomicAdd(&sH[rb + dd], pk);
        sey += (float)ec * yy;
    }

    // block-reduce sey -> global
    #pragma unroll
    for (int o = 16; o; o >>= 1)
        sey += __shfl_down_sync(0xffffffffu, sey, o);
    if (lane == 0) wA[wid] = sey;
    __syncthreads();
    if (t == 0) {
        float a = 0.f;
        #pragma unroll
        for (int w = 0; w < NWRP; w++) a += wA[w];
        atomicAdd(&g_sey, a);
    }

    // flush: unpack + sum replicas, one global atomic per non-empty bucket
    const unsigned LOWMASK = (1u << CNT_SHIFT) - 1u;
    for (int i = t; i < MAXD; i += NTHR) {
        unsigned lo = 0u, m = 0u;
        #pragma unroll
        for (int r = 0; r < NREP; r++) {
            unsigned v = sH[r * RSTR + i];
            lo += v & LOWMASK;
            m  += v >> CNT_SHIFT;
        }
        if (lo) atomicAdd(&g_S[i], (float)lo * FIX_INV);
        if (m)  atomicAdd(&g_M[i], m);
    }

    // ================= last-block finalize =================
    __threadfence();
    if (t == 0) {
        unsigned ticket = atomicAdd(&g_done, 1u);
        sIsLast = (ticket == (unsigned)(NBLK - 1)) ? 1u : 0u;
    }
    __syncthreads();
    if (!sIsLast) return;

    float*    scan = (float*)sH;                // [0..511]
    float*    redF = scan + 512;                // [0..511]
    unsigned* redN = (unsigned*)(scan + 1024);  // [0..511]

    float    s = (t < MAXD) ? __ldcg(&g_S[t]) : 0.f;
    unsigned m = (t < MAXD) ? __ldcg(&g_M[t]) : 0u;
    __syncthreads();
    scan[t] = s;
    __syncthreads();

    // Hillis-Steele inclusive suffix scan: scan[t] = sum_{j>=t} S[j]
    #pragma unroll
    for (int off = 1; off < NTHR; off <<= 1) {
        float v = (t + off < NTHR) ? scan[t + off] : 0.f;
        __syncthreads();
        scan[t] += v;
        __syncthreads();
    }

    float lg = logf(fmaxf(scan[t], 1e-12f));
    __syncthreads();
    scan[t] = (t < MAXD) ? lg : 0.f;        // logR LUT (dead corner)
    redF[t] = (float)m * ((t < MAXD) ? lg : 0.f);
    redN[t] = m;
    __syncthreads();

    #pragma unroll
    for (int off = NTHR / 2; off; off >>= 1) {
        if (t < off) {
            redF[t] += redF[t + off];
            redN[t] += redN[t + off];
        }
        __syncthreads();
    }

    unsigned nev = redN[0];

    if (nev > 0u) {
        if (t == 0) {
            float total_ll = __ldcg(&g_sey) - redF[0];
            out[0] = -total_ll / fmaxf((float)nev, 1.f);
        }
    } else {
        // dead-in-practice corner: e.sum()==0 -> e := 1e-8 everywhere
        float slr = 0.f, syl = 0.f;
        for (int i = t; i < n; i += NTHR) {
            unsigned dd = min((unsigned)dur[i], (unsigned)(MAXD - 1));
            slr += scan[dd];
            syl += pred[i];
        }
        #pragma unroll
        for (int o = 16; o; o >>= 1) {
            slr += __shfl_down_sync(0xffffffffu, slr, o);
            syl += __shfl_down_sync(0xffffffffu, syl, o);
        }
        if (lane == 0) { wA[wid] = slr; redF[wid] = syl; }
        __syncthreads();
        if (t == 0) {
            float tot = 0.f, sy = 0.f;
            #pragma unroll
            for (int w = 0; w < NWRP; w++) { tot += wA[w]; sy += redF[w]; }
            float total_ll = 1e-8f * (sy - tot);
            float n_events = fmaxf(1e-8f * (float)n, 1.f);
            out[0] = -total_ll / n_events;
        }
    }

    // re-zero globals for next graph replay
    __syncthreads();
    for (int i = t; i < MAXD; i += NTHR) { g_S[i] = 0.f; g_M[i] = 0u; }
    if (t == 0) { g_sey = 0.f; g_done = 0u; }
}

extern "C" void kernel_launch(void* const* d_in, const int* in_sizes, int n_in,
                              void* d_out, int out_size)
{
    const float* pred = (const float*)d_in[0];
    const int*   dur  = (const int*)d_in[1];
    const int*   ev   = (const int*)d_in[2];
    int n = in_sizes[0];

    cox_tma_kernel<<<NBLK, NTHR>>>(pred, dur, ev, (float*)d_out, n);
}